// round 2
// baseline (speedup 1.0000x reference)
#include <cuda_runtime.h>
#include <math.h>

#define N_NODES 50000
#define N_EDGES 800000
#define D 128
#define H 256

// ---------------- device scratch (allocation-free rule: __device__ globals) ----------------
__device__ __align__(16) float g_n[(size_t)N_NODES * D];
__device__ __align__(16) float g_e[(size_t)N_EDGES * D];
__device__ __align__(16) float g_Ps[(size_t)N_NODES * H];
__device__ __align__(16) float g_Pr[(size_t)N_NODES * H];
__device__ __align__(16) float g_Pe[(size_t)N_EDGES * H];
__device__ __align__(16) float g_agg[(size_t)N_NODES * D];

__device__ __forceinline__ float gelu_tanh(float x) {
    const float c = 0.7978845608028654f;
    float t = tanhf(c * (x + 0.044715f * x * x * x));
    return 0.5f * x * (1.0f + t);
}

__device__ __forceinline__ unsigned f2tf32(float x) {
    unsigned r;
    asm("cvt.rna.tf32.f32 %0, %1;" : "=r"(r) : "f"(x));
    return r;
}

__device__ __forceinline__ void mma8(float* c, const uint4& a, const uint2& b) {
    asm volatile("mma.sync.aligned.m16n8k8.row.col.f32.tf32.tf32.f32 "
        "{%0,%1,%2,%3}, {%4,%5,%6,%7}, {%8,%9}, {%0,%1,%2,%3};"
        : "+f"(c[0]), "+f"(c[1]), "+f"(c[2]), "+f"(c[3])
        : "r"(a.x), "r"(a.y), "r"(a.z), "r"(a.w), "r"(b.x), "r"(b.y));
}

// fragment scatter index helpers (m16n8k8):
// A element (local row r in 16-row tile, k): lane=((r&7)<<2)|(k&3), frag=(r>>3)+(((k>>2)&1)<<1)
// B element (k, n in 8-col tile): lane=((n&7)<<2)|(k&3), frag=(k>>2)&1

// =====================================================================================
// gemm1_tf32: C[M,256] = A[M,128] @ B[128,256]  (B row-major [k][n])
// block: 128 rows x 256 cols, 512 threads (16 warps, 4m x 4n), warp tile 32x64.
// smem: A-frags 64KB + B-frags 128KB = 192KB
// =====================================================================================
__global__ __launch_bounds__(512, 1)
void gemm1_tf32(const float* __restrict__ A, const float* __restrict__ B,
                float* __restrict__ C, int M)
{
    extern __shared__ unsigned smu[];
    unsigned* As = smu;            // [16 kt][8 mt][32 lane][4]  = 16384
    unsigned* Bs = smu + 16384;    // [16 kt][32 nt][32 lane][2] = 32768
    const int tid = threadIdx.x;
    const int row0 = blockIdx.x * 128;

    // stage B (128x256)
    for (int i = tid; i < 128 * 64; i += 512) {
        int k = i >> 6;
        int n0 = (i & 63) << 2;
        float4 v = ((const float4*)B)[i];
        int kt = k >> 3;
        int lp = k & 3;
        int bi = (k >> 2) & 1;
        float vv[4] = {v.x, v.y, v.z, v.w};
#pragma unroll
        for (int j = 0; j < 4; j++) {
            int n = n0 + j;
            int nt = n >> 3;
            int lane = ((n & 7) << 2) | lp;
            Bs[(((kt << 5) + nt) * 32 + lane) * 2 + bi] = f2tf32(vv[j]);
        }
    }
    // stage A (128x128 tile, zero-padded)
    for (int i = tid; i < 128 * 32; i += 512) {
        int m = i >> 5;
        int k0 = (i & 31) << 2;
        int row = row0 + m;
        float4 v = make_float4(0.f, 0.f, 0.f, 0.f);
        if (row < M) v = ((const float4*)A)[(size_t)row * 32 + (i & 31)];
        int mt = m >> 4, mr = m & 15;
        int bsel = mr >> 3, rr = mr & 7;
        float vv[4] = {v.x, v.y, v.z, v.w};
#pragma unroll
        for (int j = 0; j < 4; j++) {
            int k = k0 + j;
            int kt = k >> 3;
            int lane = (rr << 2) | (k & 3);
            int fi = bsel + (((k >> 2) & 1) << 1);
            As[(((kt << 3) + mt) * 32 + lane) * 4 + fi] = f2tf32(vv[j]);
        }
    }
    __syncthreads();

    const int w = tid >> 5, lane = tid & 31;
    const int wm = w >> 2, wn = w & 3;
    float acc[2][8][4];
#pragma unroll
    for (int i = 0; i < 2; i++)
#pragma unroll
        for (int j = 0; j < 8; j++)
#pragma unroll
            for (int q = 0; q < 4; q++) acc[i][j][q] = 0.f;

    const uint4* As4 = (const uint4*)As;
    const uint2* Bs2 = (const uint2*)Bs;
#pragma unroll
    for (int kt = 0; kt < 16; kt++) {
        uint4 a[2];
#pragma unroll
        for (int i = 0; i < 2; i++)
            a[i] = As4[(kt * 8 + wm * 2 + i) * 32 + lane];
        uint2 b[8];
#pragma unroll
        for (int j = 0; j < 8; j++)
            b[j] = Bs2[(kt * 32 + wn * 8 + j) * 32 + lane];
#pragma unroll
        for (int i = 0; i < 2; i++)
#pragma unroll
            for (int j = 0; j < 8; j++)
                mma8(acc[i][j], a[i], b[j]);
    }

    // epilogue
    const int rbase = row0 + wm * 32 + (lane >> 2);
    const int cbase = wn * 64 + (lane & 3) * 2;
#pragma unroll
    for (int i = 0; i < 2; i++) {
#pragma unroll
        for (int j = 0; j < 8; j++) {
            int r = rbase + i * 16;
            int c = cbase + j * 8;
            if (r < M)
                *(float2*)&C[(size_t)r * 256 + c] = make_float2(acc[i][j][0], acc[i][j][1]);
            if (r + 8 < M)
                *(float2*)&C[(size_t)(r + 8) * 256 + c] = make_float2(acc[i][j][2], acc[i][j][3]);
        }
    }
}

// =====================================================================================
// edge_msg_tf32: m1 = relu(Ps[s]+Pr[r]+Pe+b1) [64x256]; out = relu(m1@W2+b2) [64x128];
//                agg[rcv] += out (atomics).
// block: 64 edges, 256 threads (8 warps, 2m x 4n), warp tile 32x32, K=256 (32 kt).
// smem: A-frags 64KB + W2-frags 128KB + ridx = ~192.25KB
// =====================================================================================
__global__ __launch_bounds__(256, 1)
void edge_msg_tf32(const float* __restrict__ Ps, const float* __restrict__ Pr,
                   const float* __restrict__ Pe, const float* __restrict__ b1,
                   const float* __restrict__ w2, const float* __restrict__ b2,
                   const int* __restrict__ snd, const int* __restrict__ rcv,
                   float* __restrict__ agg, int E)
{
    extern __shared__ unsigned smu[];
    unsigned* As = smu;            // [32 kt][4 mt][32][4]  = 16384
    unsigned* Bs = smu + 16384;    // [32 kt][16 nt][32][2] = 32768
    int* ridx = (int*)(smu + 49152);
    const int tid = threadIdx.x;
    const int e0 = blockIdx.x * 64;

    // stage W2 (256x128 row-major)
    for (int i = tid; i < 256 * 32; i += 256) {
        int k = i >> 5;
        int n0 = (i & 31) << 2;
        float4 v = ((const float4*)w2)[i];
        int kt = k >> 3;
        int lp = k & 3;
        int bi = (k >> 2) & 1;
        float vv[4] = {v.x, v.y, v.z, v.w};
#pragma unroll
        for (int j = 0; j < 4; j++) {
            int n = n0 + j;
            int nt = n >> 3;
            int lane = ((n & 7) << 2) | lp;
            Bs[(((kt << 4) + nt) * 32 + lane) * 2 + bi] = f2tf32(vv[j]);
        }
    }
    if (tid < 64) ridx[tid] = (e0 + tid < E) ? rcv[e0 + tid] : 0;

    // build m1 in A-fragment layout
    for (int i = tid; i < 64 * 64; i += 256) {
        int m = i >> 6;
        int c4 = i & 63;
        int k0 = c4 << 2;
        int eg = e0 + m;
        float vv[4] = {0.f, 0.f, 0.f, 0.f};
        if (eg < E) {
            int s = snd[eg];
            int rv = rcv[eg];
            float4 ps = ((const float4*)Ps)[(size_t)s * 64 + c4];
            float4 pr = ((const float4*)Pr)[(size_t)rv * 64 + c4];
            float4 pe = ((const float4*)Pe)[(size_t)eg * 64 + c4];
            float4 bb = ((const float4*)b1)[c4];
            vv[0] = fmaxf(ps.x + pr.x + pe.x + bb.x, 0.f);
            vv[1] = fmaxf(ps.y + pr.y + pe.y + bb.y, 0.f);
            vv[2] = fmaxf(ps.z + pr.z + pe.z + bb.z, 0.f);
            vv[3] = fmaxf(ps.w + pr.w + pe.w + bb.w, 0.f);
        }
        int mt = m >> 4, mr = m & 15;
        int bsel = mr >> 3, rr = mr & 7;
#pragma unroll
        for (int j = 0; j < 4; j++) {
            int k = k0 + j;
            int kt = k >> 3;
            int lane = (rr << 2) | (k & 3);
            int fi = bsel + (((k >> 2) & 1) << 1);
            As[(((kt << 2) + mt) * 32 + lane) * 4 + fi] = f2tf32(vv[j]);
        }
    }
    __syncthreads();

    const int w = tid >> 5, lane = tid & 31;
    const int wm = w >> 2, wn = w & 3;   // wm 0..1, wn 0..3
    float acc[2][4][4];
#pragma unroll
    for (int i = 0; i < 2; i++)
#pragma unroll
        for (int j = 0; j < 4; j++)
#pragma unroll
            for (int q = 0; q < 4; q++) acc[i][j][q] = 0.f;

    const uint4* As4 = (const uint4*)As;
    const uint2* Bs2 = (const uint2*)Bs;
#pragma unroll
    for (int kt = 0; kt < 32; kt++) {
        uint4 a[2];
#pragma unroll
        for (int i = 0; i < 2; i++)
            a[i] = As4[(kt * 4 + wm * 2 + i) * 32 + lane];
        uint2 b[4];
#pragma unroll
        for (int j = 0; j < 4; j++)
            b[j] = Bs2[(kt * 16 + wn * 4 + j) * 32 + lane];
#pragma unroll
        for (int i = 0; i < 2; i++)
#pragma unroll
            for (int j = 0; j < 4; j++)
                mma8(acc[i][j], a[i], b[j]);
    }

    // epilogue: bias + relu + atomic scatter
    const int rbase = wm * 32 + (lane >> 2);
    const int cbase = wn * 32 + (lane & 3) * 2;
#pragma unroll
    for (int i = 0; i < 2; i++) {
#pragma unroll
        for (int j = 0; j < 4; j++) {
            int c = cbase + j * 8;
            float2 bv = *(const float2*)&b2[c];
            int r = rbase + i * 16;
            if (e0 + r < E) {
                float* dst = agg + (size_t)ridx[r] * 128 + c;
                atomicAdd(dst + 0, fmaxf(acc[i][j][0] + bv.x, 0.f));
                atomicAdd(dst + 1, fmaxf(acc[i][j][1] + bv.y, 0.f));
            }
            if (e0 + r + 8 < E) {
                float* dst = agg + (size_t)ridx[r + 8] * 128 + c;
                atomicAdd(dst + 0, fmaxf(acc[i][j][2] + bv.x, 0.f));
                atomicAdd(dst + 1, fmaxf(acc[i][j][3] + bv.y, 0.f));
            }
        }
    }
}

// =====================================================================================
// embed_tf32: out = LayerNorm(gelu(x @ W + b))  W: [128,128]
// block: 64 rows x 128 cols, 256 threads (8 warps, 2m x 4n), warp tile 32x32, K=128.
// smem: A-frags 32KB + W-frags 64KB + ys 32KB = 128KB
// =====================================================================================
__global__ __launch_bounds__(256, 1)
void embed_tf32(const float* __restrict__ x, const float* __restrict__ wg,
                const float* __restrict__ bias,
                const float* __restrict__ lns, const float* __restrict__ lno,
                float* __restrict__ out, int nrows)
{
    extern __shared__ unsigned smu[];
    unsigned* As = smu;            // [16 kt][4 mt][32][4]  = 8192
    unsigned* Ws = smu + 8192;     // [16 kt][16 nt][32][2] = 16384
    float* ys = (float*)(smu + 24576);  // 64*128
    const int tid = threadIdx.x;
    const int row0 = blockIdx.x * 64;

    // stage W (128x128 row-major)
    for (int i = tid; i < 128 * 32; i += 256) {
        int k = i >> 5;
        int n0 = (i & 31) << 2;
        float4 v = ((const float4*)wg)[i];
        int kt = k >> 3;
        int lp = k & 3;
        int bi = (k >> 2) & 1;
        float vv[4] = {v.x, v.y, v.z, v.w};
#pragma unroll
        for (int j = 0; j < 4; j++) {
            int n = n0 + j;
            int nt = n >> 3;
            int lane = ((n & 7) << 2) | lp;
            Ws[(((kt << 4) + nt) * 32 + lane) * 2 + bi] = f2tf32(vv[j]);
        }
    }
    // stage x tile (64x128)
    for (int i = tid; i < 64 * 32; i += 256) {
        int m = i >> 5;
        int k0 = (i & 31) << 2;
        int row = row0 + m;
        float4 v = make_float4(0.f, 0.f, 0.f, 0.f);
        if (row < nrows) v = ((const float4*)x)[(size_t)row * 32 + (i & 31)];
        int mt = m >> 4, mr = m & 15;
        int bsel = mr >> 3, rr = mr & 7;
        float vv[4] = {v.x, v.y, v.z, v.w};
#pragma unroll
        for (int j = 0; j < 4; j++) {
            int k = k0 + j;
            int kt = k >> 3;
            int lane = (rr << 2) | (k & 3);
            int fi = bsel + (((k >> 2) & 1) << 1);
            As[(((kt << 2) + mt) * 32 + lane) * 4 + fi] = f2tf32(vv[j]);
        }
    }
    __syncthreads();

    const int w = tid >> 5, lane = tid & 31;
    const int wm = w >> 2, wn = w & 3;
    float acc[2][4][4];
#pragma unroll
    for (int i = 0; i < 2; i++)
#pragma unroll
        for (int j = 0; j < 4; j++)
#pragma unroll
            for (int q = 0; q < 4; q++) acc[i][j][q] = 0.f;

    const uint4* As4 = (const uint4*)As;
    const uint2* Ws2 = (const uint2*)Ws;
#pragma unroll
    for (int kt = 0; kt < 16; kt++) {
        uint4 a[2];
#pragma unroll
        for (int i = 0; i < 2; i++)
            a[i] = As4[(kt * 4 + wm * 2 + i) * 32 + lane];
        uint2 b[4];
#pragma unroll
        for (int j = 0; j < 4; j++)
            b[j] = Ws2[(kt * 16 + wn * 4 + j) * 32 + lane];
#pragma unroll
        for (int i = 0; i < 2; i++)
#pragma unroll
            for (int j = 0; j < 4; j++)
                mma8(acc[i][j], a[i], b[j]);
    }

    // gelu(acc + bias) -> ys
    const int rbase = wm * 32 + (lane >> 2);
    const int cbase = wn * 32 + (lane & 3) * 2;
#pragma unroll
    for (int i = 0; i < 2; i++) {
#pragma unroll
        for (int j = 0; j < 4; j++) {
            int c = cbase + j * 8;
            float2 bv = *(const float2*)&bias[c];
            int r = rbase + i * 16;
            ys[r * 128 + c + 0] = gelu_tanh(acc[i][j][0] + bv.x);
            ys[r * 128 + c + 1] = gelu_tanh(acc[i][j][1] + bv.y);
            ys[(r + 8) * 128 + c + 0] = gelu_tanh(acc[i][j][2] + bv.x);
            ys[(r + 8) * 128 + c + 1] = gelu_tanh(acc[i][j][3] + bv.y);
        }
    }
    __syncthreads();

    // LayerNorm: 8 warps x 8 rows each
    float4 sc = ((const float4*)lns)[lane];
    float4 of = ((const float4*)lno)[lane];
#pragma unroll
    for (int rr = 0; rr < 8; rr++) {
        int r = w * 8 + rr;
        float4 v = ((float4*)ys)[r * 32 + lane];
        float s = v.x + v.y + v.z + v.w;
#pragma unroll
        for (int o = 16; o; o >>= 1) s += __shfl_xor_sync(0xffffffffu, s, o);
        float mean = s * (1.0f / 128.0f);
        float dx = v.x - mean, dy = v.y - mean, dz = v.z - mean, dw = v.w - mean;
        float q = dx * dx + dy * dy + dz * dz + dw * dw;
#pragma unroll
        for (int o = 16; o; o >>= 1) q += __shfl_xor_sync(0xffffffffu, q, o);
        float rstd = rsqrtf(q * (1.0f / 128.0f) + 1e-5f);
        int row = row0 + r;
        if (row < nrows) {
            float4 o4;
            o4.x = dx * rstd * sc.x + of.x;
            o4.y = dy * rstd * sc.y + of.y;
            o4.z = dz * rstd * sc.z + of.z;
            o4.w = dw * rstd * sc.w + of.w;
            ((float4*)out)[(size_t)row * 32 + lane] = o4;
        }
    }
}

// =====================================================================================
// node_update (fp32): upd = LN(concat(n, agg) @ W + b); n_out = n + upd.  32 rows / CTA.
// =====================================================================================
__global__ __launch_bounds__(256, 1)
void node_update_kernel(const float* __restrict__ n_in, const float* __restrict__ agg,
                        const float* __restrict__ W, const float* __restrict__ bias,
                        const float* __restrict__ lns, const float* __restrict__ lno,
                        float* __restrict__ n_out, int N)
{
    extern __shared__ float sm[];
    float* Ws = sm;                 // 256*128
    float* xs = Ws + 256 * 128;     // 32*256
    float* ys = xs + 32 * 256;      // 32*128
    const int tid = threadIdx.x;
    const int row0 = blockIdx.x * 32;

    for (int i = tid; i < 256 * 128 / 4; i += 256)
        ((float4*)Ws)[i] = ((const float4*)W)[i];
    for (int i = tid; i < 32 * 64; i += 256) {
        int r = i >> 6, c4 = i & 63;
        int row = row0 + r;
        float4 v = make_float4(0.f, 0.f, 0.f, 0.f);
        if (row < N) {
            if (c4 < 32) v = ((const float4*)n_in)[(size_t)row * 32 + c4];
            else         v = ((const float4*)agg)[(size_t)row * 32 + (c4 - 32)];
        }
        ((float4*)xs)[i] = v;
    }
    __syncthreads();

    const int tr = tid >> 5;
    const int tc = tid & 31;
    float acc[4][4];
#pragma unroll
    for (int i = 0; i < 4; i++)
#pragma unroll
        for (int j = 0; j < 4; j++) acc[i][j] = 0.f;

    for (int k = 0; k < 256; k += 4) {
        float4 a[4];
#pragma unroll
        for (int i = 0; i < 4; i++) a[i] = *(float4*)&xs[(tr * 4 + i) * 256 + k];
#pragma unroll
        for (int kk = 0; kk < 4; kk++) {
            float4 b = *(float4*)&Ws[(k + kk) * 128 + tc * 4];
#pragma unroll
            for (int i = 0; i < 4; i++) {
                float av = ((float*)&a[i])[kk];
                acc[i][0] += av * b.x; acc[i][1] += av * b.y;
                acc[i][2] += av * b.z; acc[i][3] += av * b.w;
            }
        }
    }
    float4 bv = ((const float4*)bias)[tc];
#pragma unroll
    for (int i = 0; i < 4; i++) {
        int r = tr * 4 + i;
        ys[r * 128 + tc * 4 + 0] = acc[i][0] + bv.x;
        ys[r * 128 + tc * 4 + 1] = acc[i][1] + bv.y;
        ys[r * 128 + tc * 4 + 2] = acc[i][2] + bv.z;
        ys[r * 128 + tc * 4 + 3] = acc[i][3] + bv.w;
    }
    __syncthreads();

    const int wid = tid >> 5, lane = tid & 31;
    float4 sc = ((const float4*)lns)[lane];
    float4 of = ((const float4*)lno)[lane];
#pragma unroll
    for (int rr = 0; rr < 4; rr++) {
        int r = wid * 4 + rr;
        float4 v = ((float4*)ys)[r * 32 + lane];
        float s = v.x + v.y + v.z + v.w;
#pragma unroll
        for (int o = 16; o; o >>= 1) s += __shfl_xor_sync(0xffffffffu, s, o);
        float mean = s * (1.0f / 128.0f);
        float dx = v.x - mean, dy = v.y - mean, dz = v.z - mean, dw = v.w - mean;
        float q = dx * dx + dy * dy + dz * dz + dw * dw;
#pragma unroll
        for (int o = 16; o; o >>= 1) q += __shfl_xor_sync(0xffffffffu, q, o);
        float rstd = rsqrtf(q * (1.0f / 128.0f) + 1e-5f);
        int row = row0 + r;
        if (row < N) {
            float4 res = *(float4*)&xs[r * 256 + lane * 4];
            float4 o4;
            o4.x = res.x + dx * rstd * sc.x + of.x;
            o4.y = res.y + dy * rstd * sc.y + of.y;
            o4.z = res.z + dz * rstd * sc.z + of.z;
            o4.w = res.w + dw * rstd * sc.w + of.w;
            ((float4*)n_out)[(size_t)row * 32 + lane] = o4;
        }
    }
}

// =====================================================================================
extern "C" void kernel_launch(void* const* d_in, const int* in_sizes, int n_in,
                              void* d_out, int out_size)
{
    const float* nodes     = (const float*)d_in[0];
    const float* edges     = (const float*)d_in[1];
    const int*   senders   = (const int*)d_in[2];
    const int*   receivers = (const int*)d_in[3];
    const float* w_node    = (const float*)d_in[4];
    const float* b_node    = (const float*)d_in[5];
    const float* w_edge    = (const float*)d_in[6];
    const float* b_edge    = (const float*)d_in[7];
    const float* ln_n_s    = (const float*)d_in[8];
    const float* ln_n_o    = (const float*)d_in[9];
    const float* ln_e_s    = (const float*)d_in[10];
    const float* ln_e_o    = (const float*)d_in[11];
    const float* msg_w1    = (const float*)d_in[12];
    const float* msg_b1    = (const float*)d_in[13];
    const float* msg_w2    = (const float*)d_in[14];
    const float* msg_b2    = (const float*)d_in[15];
    const float* upd_w     = (const float*)d_in[16];
    const float* upd_b     = (const float*)d_in[17];
    const float* ln_s      = (const float*)d_in[18];
    const float* ln_o      = (const float*)d_in[19];

    const int N = in_sizes[0] / D;
    const int E = in_sizes[1] / D;

    float *pn, *pe, *pPs, *pPr, *pPe, *pagg;
    cudaGetSymbolAddress((void**)&pn,   g_n);
    cudaGetSymbolAddress((void**)&pe,   g_e);
    cudaGetSymbolAddress((void**)&pPs,  g_Ps);
    cudaGetSymbolAddress((void**)&pPr,  g_Pr);
    cudaGetSymbolAddress((void**)&pPe,  g_Pe);
    cudaGetSymbolAddress((void**)&pagg, g_agg);

    const size_t embed_smem = 131072;                                   // 128KB
    const size_t gemm1_smem = 196608;                                   // 192KB
    const size_t msg_smem   = 196608 + 256;                             // ~192.25KB
    const size_t upd_smem   = (size_t)(256 * 128 + 32 * 256 + 32 * 128) * 4;  // 176KB

    cudaFuncSetAttribute(embed_tf32,        cudaFuncAttributeMaxDynamicSharedMemorySize, (int)embed_smem);
    cudaFuncSetAttribute(gemm1_tf32,        cudaFuncAttributeMaxDynamicSharedMemorySize, (int)gemm1_smem);
    cudaFuncSetAttribute(edge_msg_tf32,     cudaFuncAttributeMaxDynamicSharedMemorySize, (int)msg_smem);
    cudaFuncSetAttribute(node_update_kernel,cudaFuncAttributeMaxDynamicSharedMemorySize, (int)upd_smem);

    embed_tf32<<<(N + 63) / 64, 256, embed_smem>>>(nodes, w_node, b_node, ln_n_s, ln_n_o, pn, N);
    embed_tf32<<<(E + 63) / 64, 256, embed_smem>>>(edges, w_edge, b_edge, ln_e_s, ln_e_o, pe, E);

    for (int l = 0; l < 3; l++) {
        const float* w1 = msg_w1 + (size_t)l * 384 * 256;
        gemm1_tf32<<<(N + 127) / 128, 512, gemm1_smem>>>(pn, w1,             pPs, N);
        gemm1_tf32<<<(N + 127) / 128, 512, gemm1_smem>>>(pn, w1 + 128 * 256, pPr, N);
        gemm1_tf32<<<(E + 127) / 128, 512, gemm1_smem>>>(pe, w1 + 256 * 256, pPe, E);
        cudaMemsetAsync(pagg, 0, (size_t)N * D * sizeof(float), 0);
        edge_msg_tf32<<<(E + 63) / 64, 256, msg_smem>>>(
            pPs, pPr, pPe, msg_b1 + (size_t)l * 256,
            msg_w2 + (size_t)l * 256 * 128, msg_b2 + (size_t)l * 128,
            senders, receivers, pagg, E);
        float* nout = (l == 2) ? (float*)d_out : pn;
        node_update_kernel<<<(N + 31) / 32, 256, upd_smem>>>(
            pn, pagg, upd_w + (size_t)l * 256 * 128, upd_b + (size_t)l * 128,
            ln_s + (size_t)l * 128, ln_o + (size_t)l * 128, nout, N);
    }
}

// round 5
// speedup vs baseline: 4.1105x; 4.1105x over previous
#include <cuda_runtime.h>
#include <cuda_fp16.h>
#include <stdint.h>
#include <math.h>

#define N_NODES 50000
#define N_EDGES 800000
#define D 128
#define H 256

// ---------------- device scratch (allocation-free rule: __device__ globals) ----------------
__device__ __align__(16) float  g_n  [(size_t)N_NODES * D];
__device__ __align__(16) __half g_nh [(size_t)N_NODES * D];
__device__ __align__(16) __half g_eh [(size_t)N_EDGES * D];
__device__ __align__(16) __half g_Psh[(size_t)N_NODES * H];
__device__ __align__(16) __half g_Prh[(size_t)N_NODES * H];
__device__ __align__(16) __half g_Peh[(size_t)N_EDGES * H];
__device__ __align__(16) float  g_agg[(size_t)N_NODES * D];
// pre-transposed fp16 weights ([N][K] K-major)
__device__ __align__(16) __half g_wnt[128 * 128];
__device__ __align__(16) __half g_wet[128 * 128];
__device__ __align__(16) __half g_w1t[9 * 256 * 128];
__device__ __align__(16) __half g_w2t[3 * 128 * 256];
__device__ __align__(16) __half g_wut[3 * 128 * 256];

__device__ __forceinline__ uint32_t s2u(const void* p) {
    uint32_t a;
    asm("{ .reg .u64 t; cvta.to.shared.u64 t, %1; cvt.u32.u64 %0, t; }" : "=r"(a) : "l"(p));
    return a;
}

__device__ __forceinline__ void ldsm4(uint32_t* r, uint32_t a) {
    asm volatile("ldmatrix.sync.aligned.m8n8.x4.shared.b16 {%0,%1,%2,%3}, [%4];"
        : "=r"(r[0]), "=r"(r[1]), "=r"(r[2]), "=r"(r[3]) : "r"(a));
}

__device__ __forceinline__ void mma16816(float* c, const uint32_t* a, uint32_t b0, uint32_t b1) {
    asm volatile("mma.sync.aligned.m16n8k16.row.col.f32.f16.f16.f32 "
        "{%0,%1,%2,%3},{%4,%5,%6,%7},{%8,%9},{%0,%1,%2,%3};"
        : "+f"(c[0]), "+f"(c[1]), "+f"(c[2]), "+f"(c[3])
        : "r"(a[0]), "r"(a[1]), "r"(a[2]), "r"(a[3]), "r"(b0), "r"(b1));
}

__device__ __forceinline__ float gelu_tanh(float x) {
    const float c = 0.7978845608028654f;
    float t = tanhf(c * (x + 0.044715f * x * x * x));
    return 0.5f * x * (1.0f + t);
}

// ------------- shared-memory GEMM core -------------
// A tile: 128 rows x K f16, row stride SA = K*2+16 bytes (pad keeps ldmatrix conflict-free).
// B tile: N rows (output cols) x K f16, same stride.
// 512 threads = 16 warps as 4m x 4n; warp tile = 32 rows x (8*NTW) cols.
// NTW = 8 for N=256, 4 for N=128.
template<int K, int NTW>
__device__ __forceinline__ void mma_loop(uint32_t abase, uint32_t bbase,
                                         float (&acc)[2][NTW][4], int wm, int wn, int lane)
{
    const int SA = K * 2 + 16;
    int mat  = lane >> 3;
    int arow = (lane & 7) + ((mat & 1) << 3);
    int akb  = (mat >> 1) << 4;
    int brow = (lane & 7) + ((mat >> 1) << 3);
    int bkb  = (mat & 1) << 4;
    uint32_t a0 = abase + (wm * 32 + arow) * SA + akb;
    uint32_t b0 = bbase + (wn * (8 * NTW) + brow) * SA + bkb;
#pragma unroll
    for (int kt = 0; kt < K / 16; kt++) {
        uint32_t A[2][4], B[NTW / 2][4];
        ldsm4(A[0], a0 + kt * 32);
        ldsm4(A[1], a0 + 16 * SA + kt * 32);
#pragma unroll
        for (int j = 0; j < NTW / 2; j++)
            ldsm4(B[j], b0 + j * 16 * SA + kt * 32);
#pragma unroll
        for (int i = 0; i < 2; i++)
#pragma unroll
            for (int j = 0; j < NTW / 2; j++) {
                mma16816(acc[i][2 * j],     A[i], B[j][0], B[j][1]);
                mma16816(acc[i][2 * j + 1], A[i], B[j][2], B[j][3]);
            }
    }
}

// stage f16 rows (gmem, K per row) into padded smem tile; zero-pad beyond M
template<int K>
__device__ __forceinline__ void stage_rows(char* dst, const __half* src, size_t row0, int M)
{
    const int SA = K * 2 + 16, CH = K / 8;
    for (int i = threadIdx.x; i < 128 * CH; i += 512) {
        int r = i / CH, c = i % CH;
        uint4 v = make_uint4(0, 0, 0, 0);
        if (row0 + r < (size_t)M) v = *(const uint4*)(src + (row0 + r) * K + c * 8);
        *(uint4*)(dst + r * SA + c * 16) = v;
    }
}
// stage weight matrix (rows x K f16, contiguous) into padded smem
template<int K>
__device__ __forceinline__ void stage_w(char* dst, const __half* src, int rows)
{
    const int SA = K * 2 + 16, CH = K / 8;
    for (int i = threadIdx.x; i < rows * CH; i += 512)
        *(uint4*)(dst + (i / CH) * SA + (i % CH) * 16) = ((const uint4*)src)[i];
}

// =====================================================================================
// transpose+convert: out[n][k] (f16) = in[k][n] (f32), dims K x N
// =====================================================================================
__global__ void transpose_w(const float* __restrict__ in, __half* __restrict__ out, int K, int N)
{
    __shared__ float t[32][33];
    int k0 = blockIdx.x * 32, n0 = blockIdx.y * 32;
    int tx = threadIdx.x & 31, ty = threadIdx.x >> 5;
    for (int i = ty; i < 32; i += 8) {
        int k = k0 + i, n = n0 + tx;
        t[i][tx] = (k < K && n < N) ? in[(size_t)k * N + n] : 0.f;
    }
    __syncthreads();
    for (int i = ty; i < 32; i += 8) {
        int n = n0 + i, k = k0 + tx;
        if (n < N && k < K) out[(size_t)n * K + k] = __float2half(t[tx][i]);
    }
}

// =====================================================================================
// embed: out = LN(gelu(x@W + b)). x f32 [M,128], Wt f16 [128][128]. K=128, N=128.
// smem: A 34816 + B 34816 (Csm f32 128x132 overlays A+B after sync)
// =====================================================================================
__global__ __launch_bounds__(512, 1)
void embed_f16(const float* __restrict__ x, const __half* __restrict__ Wt,
               const float* __restrict__ bias,
               const float* __restrict__ lns, const float* __restrict__ lno,
               float* __restrict__ outf, __half* __restrict__ outh, int M)
{
    extern __shared__ char sm[];
    char* Asm = sm;
    char* Bsm = sm + 34816;
    const int tid = threadIdx.x, w = tid >> 5, lane = tid & 31;
    const size_t row0 = (size_t)blockIdx.x * 128;

    // stage A: f32 -> f16
    for (int i = tid; i < 128 * 16; i += 512) {
        int r = i >> 4, c = i & 15;
        uint32_t o[4] = {0, 0, 0, 0};
        if (row0 + r < (size_t)M) {
            const float* src = x + (row0 + r) * 128 + c * 8;
            float4 a = ((const float4*)src)[0], b = ((const float4*)src)[1];
            __half2 h0 = __floats2half2_rn(a.x, a.y), h1 = __floats2half2_rn(a.z, a.w);
            __half2 h2 = __floats2half2_rn(b.x, b.y), h3 = __floats2half2_rn(b.z, b.w);
            o[0] = *(uint32_t*)&h0; o[1] = *(uint32_t*)&h1; o[2] = *(uint32_t*)&h2; o[3] = *(uint32_t*)&h3;
        }
        *(uint4*)(Asm + r * 272 + c * 16) = *(uint4*)o;
    }
    stage_w<128>(Bsm, Wt, 128);
    __syncthreads();

    float acc[2][4][4] = {};
    mma_loop<128, 4>(s2u(Asm), s2u(Bsm), acc, w >> 2, w & 3, lane);
    __syncthreads();   // everyone done reading A/B

    float* Csm = (float*)sm;   // 128 x 132
    const int gid = lane >> 2, tig = lane & 3;
    const int rb = (w >> 2) * 32 + gid, cb = (w & 3) * 32 + tig * 2;
#pragma unroll
    for (int i = 0; i < 2; i++)
#pragma unroll
        for (int nt = 0; nt < 4; nt++) {
            int col = cb + nt * 8;
            int r = rb + i * 16;
            Csm[r * 132 + col]       = gelu_tanh(acc[i][nt][0] + bias[col]);
            Csm[r * 132 + col + 1]   = gelu_tanh(acc[i][nt][1] + bias[col + 1]);
            Csm[(r + 8) * 132 + col]     = gelu_tanh(acc[i][nt][2] + bias[col]);
            Csm[(r + 8) * 132 + col + 1] = gelu_tanh(acc[i][nt][3] + bias[col + 1]);
        }
    __syncthreads();

    // LayerNorm: 4 threads per row; thread s owns cols s*4 + k*16
    int r = tid >> 2, s = tid & 3;
    float4 v[8];
    float sum = 0.f;
#pragma unroll
    for (int k = 0; k < 8; k++) {
        v[k] = *(float4*)&Csm[r * 132 + s * 4 + k * 16];
        sum += v[k].x + v[k].y + v[k].z + v[k].w;
    }
    sum += __shfl_xor_sync(0xffffffffu, sum, 1);
    sum += __shfl_xor_sync(0xffffffffu, sum, 2);
    float mean = sum * (1.0f / 128.0f);
    float q = 0.f;
#pragma unroll
    for (int k = 0; k < 8; k++) {
        float dx = v[k].x - mean, dy = v[k].y - mean, dz = v[k].z - mean, dw = v[k].w - mean;
        q += dx * dx + dy * dy + dz * dz + dw * dw;
    }
    q += __shfl_xor_sync(0xffffffffu, q, 1);
    q += __shfl_xor_sync(0xffffffffu, q, 2);
    float rstd = rsqrtf(q * (1.0f / 128.0f) + 1e-5f);

    size_t row = row0 + r;
    if (row < (size_t)M) {
#pragma unroll
        for (int k = 0; k < 8; k++) {
            int col = s * 4 + k * 16;
            float4 sc = *(const float4*)(lns + col), of = *(const float4*)(lno + col);
            float4 o;
            o.x = (v[k].x - mean) * rstd * sc.x + of.x;
            o.y = (v[k].y - mean) * rstd * sc.y + of.y;
            o.z = (v[k].z - mean) * rstd * sc.z + of.z;
            o.w = (v[k].w - mean) * rstd * sc.w + of.w;
            if (outf) *(float4*)(outf + row * 128 + col) = o;
            if (outh) {
                __half2 h0 = __floats2half2_rn(o.x, o.y), h1 = __floats2half2_rn(o.z, o.w);
                ((uint32_t*)(outh + row * 128 + col))[0] = *(uint32_t*)&h0;
                ((uint32_t*)(outh + row * 128 + col))[1] = *(uint32_t*)&h1;
            }
        }
    }
}

// =====================================================================================
// gemm1: C[M,256] (f16) = A[M,128] (f16) @ Bt[256][128]. K=128, N=256.
// smem: A 34816 + B 69632 = 104448
// =====================================================================================
__global__ __launch_bounds__(512, 1)
void gemm1_f16(const __half* __restrict__ A, const __half* __restrict__ Bt,
               __half* __restrict__ C, int M)
{
    extern __shared__ char sm[];
    char* Asm = sm;
    char* Bsm = sm + 34816;
    const int tid = threadIdx.x, w = tid >> 5, lane = tid & 31;
    const size_t row0 = (size_t)blockIdx.x * 128;

    stage_rows<128>(Asm, A, row0, M);
    stage_w<128>(Bsm, Bt, 256);
    __syncthreads();

    float acc[2][8][4] = {};
    mma_loop<128, 8>(s2u(Asm), s2u(Bsm), acc, w >> 2, w & 3, lane);

    const int gid = lane >> 2, tig = lane & 3;
    const int rb = (w >> 2) * 32 + gid, cb = (w & 3) * 64 + tig * 2;
#pragma unroll
    for (int i = 0; i < 2; i++) {
        size_t r = row0 + rb + i * 16;
#pragma unroll
        for (int nt = 0; nt < 8; nt++) {
            int col = cb + nt * 8;
            __half2 h01 = __floats2half2_rn(acc[i][nt][0], acc[i][nt][1]);
            __half2 h23 = __floats2half2_rn(acc[i][nt][2], acc[i][nt][3]);
            if (r < (size_t)M)     *(__half2*)(C + r * 256 + col) = h01;
            if (r + 8 < (size_t)M) *(__half2*)(C + (r + 8) * 256 + col) = h23;
        }
    }
}

// =====================================================================================
// edge_msg: m1 = relu(Ps[s]+Pr[r]+Pe+b1) [128x256]; out = relu(m1@W2+b2) [128x128];
//           agg[rcv] += out (float4 atomics). K=256, N=128.
// smem: idx 1024 + A 67584 + B 67584 = 136192 (Csm overlays A)
// =====================================================================================
__global__ __launch_bounds__(512, 1)
void edge_msg_f16(const __half* __restrict__ Ps, const __half* __restrict__ Pr,
                  const __half* __restrict__ Pe, const float* __restrict__ b1,
                  const __half* __restrict__ W2t, const float* __restrict__ b2,
                  const int* __restrict__ snd, const int* __restrict__ rcv,
                  float* __restrict__ agg, int E)
{
    extern __shared__ char sm[];
    int* sidx = (int*)sm;
    int* ridx = (int*)(sm + 512);
    char* Asm = sm + 1024;
    char* Bsm = sm + 1024 + 67584;
    const int tid = threadIdx.x, w = tid >> 5, lane = tid & 31;
    const int e0 = blockIdx.x * 128;

    if (tid < 128) {
        int eg = e0 + tid;
        sidx[tid] = (eg < E) ? snd[eg] : -1;
        ridx[tid] = (eg < E) ? rcv[eg] : -1;
    }
    stage_w<256>(Bsm, W2t, 128);
    __syncthreads();   // indices visible

    // build m1 into A (padded, SA=528)
    for (int i = tid; i < 128 * 32; i += 512) {
        int r = i >> 5, c = i & 31, k0 = c * 8;
        int eg = e0 + r;
        uint32_t o[4] = {0, 0, 0, 0};
        if (eg < E) {
            int sv = sidx[r], rv = ridx[r];
            uint4 pa = *(const uint4*)(Ps + (size_t)sv * 256 + k0);
            uint4 pb = *(const uint4*)(Pr + (size_t)rv * 256 + k0);
            uint4 pc = *(const uint4*)(Pe + (size_t)eg * 256 + k0);
            float bv[8];
            *(float4*)bv       = *(const float4*)(b1 + k0);
            *(float4*)(bv + 4) = *(const float4*)(b1 + k0 + 4);
#pragma unroll
            for (int qq = 0; qq < 4; qq++) {
                float2 fa = __half22float2(((const __half2*)&pa)[qq]);
                float2 fb = __half22float2(((const __half2*)&pb)[qq]);
                float2 fc = __half22float2(((const __half2*)&pc)[qq]);
                float xx = fmaxf(fa.x + fb.x + fc.x + bv[2 * qq], 0.f);
                float yy = fmaxf(fa.y + fb.y + fc.y + bv[2 * qq + 1], 0.f);
                __half2 h = __floats2half2_rn(xx, yy);
                o[qq] = *(uint32_t*)&h;
            }
        }
        *(uint4*)(Asm + r * 528 + c * 16) = *(uint4*)o;
    }
    __syncthreads();

    float acc[2][4][4] = {};
    mma_loop<256, 4>(s2u(Asm), s2u(Bsm), acc, w >> 2, w & 3, lane);
    __syncthreads();   // all reads of A done

    float* Csm = (float*)Asm;   // 128 x 132 f32
    const int gid = lane >> 2, tig = lane & 3;
    const int rb = (w >> 2) * 32 + gid, cb = (w & 3) * 32 + tig * 2;
#pragma unroll
    for (int i = 0; i < 2; i++)
#pragma unroll
        for (int nt = 0; nt < 4; nt++) {
            int col = cb + nt * 8;
            int r = rb + i * 16;
            Csm[r * 132 + col]           = acc[i][nt][0];
            Csm[r * 132 + col + 1]       = acc[i][nt][1];
            Csm[(r + 8) * 132 + col]     = acc[i][nt][2];
            Csm[(r + 8) * 132 + col + 1] = acc[i][nt][3];
        }
    __syncthreads();

    // scatter: one warp per row, float4 RED
    for (int i = tid; i < 128 * 32; i += 512) {
        int r = i >> 5, c4 = i & 31;
        int rv = ridx[r];
        if (rv >= 0) {
            float4 vv = *(float4*)&Csm[r * 132 + c4 * 4];
            float4 bb = ((const float4*)b2)[c4];
            float4 o;
            o.x = fmaxf(vv.x + bb.x, 0.f);
            o.y = fmaxf(vv.y + bb.y, 0.f);
            o.z = fmaxf(vv.z + bb.z, 0.f);
            o.w = fmaxf(vv.w + bb.w, 0.f);
            atomicAdd((float4*)(agg + (size_t)rv * 128 + c4 * 4), o);
        }
    }
}

// =====================================================================================
// node_update: upd = LN(concat(nh, agg) @ Wu + b); out = n + upd. K=256, N=128.
// smem: A 67584 + B 67584 = 135168 (Csm overlays A)
// =====================================================================================
__global__ __launch_bounds__(512, 1)
void node_update_f16(const float* __restrict__ nf, const __half* __restrict__ nh,
                     const float* __restrict__ agg, const __half* __restrict__ Wut,
                     const float* __restrict__ bias,
                     const float* __restrict__ lns, const float* __restrict__ lno,
                     float* __restrict__ outf, __half* __restrict__ outh, int M)
{
    extern __shared__ char sm[];
    char* Asm = sm;
    char* Bsm = sm + 67584;
    const int tid = threadIdx.x, w = tid >> 5, lane = tid & 31;
    const size_t row0 = (size_t)blockIdx.x * 128;

    for (int i = tid; i < 128 * 32; i += 512) {
        int r = i >> 5, c = i & 31, k0 = c * 8;
        uint32_t o[4] = {0, 0, 0, 0};
        size_t row = row0 + r;
        if (row < (size_t)M) {
            if (k0 < 128) {
                *(uint4*)o = *(const uint4*)(nh + row * 128 + k0);
            } else {
                const float* src = agg + row * 128 + (k0 - 128);
                float4 a = ((const float4*)src)[0], b = ((const float4*)src)[1];
                __half2 h0 = __floats2half2_rn(a.x, a.y), h1 = __floats2half2_rn(a.z, a.w);
                __half2 h2 = __floats2half2_rn(b.x, b.y), h3 = __floats2half2_rn(b.z, b.w);
                o[0] = *(uint32_t*)&h0; o[1] = *(uint32_t*)&h1; o[2] = *(uint32_t*)&h2; o[3] = *(uint32_t*)&h3;
            }
        }
        *(uint4*)(Asm + r * 528 + c * 16) = *(uint4*)o;
    }
    stage_w<256>(Bsm, Wut, 128);
    __syncthreads();

    float acc[2][4][4] = {};
    mma_loop<256, 4>(s2u(Asm), s2u(Bsm), acc, w >> 2, w & 3, lane);
    __syncthreads();

    float* Csm = (float*)Asm;
    const int gid = lane >> 2, tig = lane & 3;
    const int rb = (w >> 2) * 32 + gid, cb = (w & 3) * 32 + tig * 2;
#pragma unroll
    for (int i = 0; i < 2; i++)
#pragma unroll
        for (int nt = 0; nt < 4; nt++) {
            int col = cb + nt * 8;
            int r = rb + i * 16;
            Csm[r * 132 + col]           = acc[i][nt][0] + bias[col];
            Csm[r * 132 + col + 1]       = acc[i][nt][1] + bias[col + 1];
            Csm[(r + 8) * 132 + col]     = acc[i][nt][2] + bias[col];
            Csm[(r + 8) * 132 + col + 1] = acc[i][nt][3] + bias[col + 1];
        }
    __syncthreads();

    int r = tid >> 2, s = tid & 3;
    float4 v[8];
    float sum = 0.f;
#pragma unroll
    for (int k = 0; k < 8; k++) {
        v[k] = *(float4*)&Csm[r * 132 + s * 4 + k * 16];
        sum += v[k].x + v[k].y + v[k].z + v[k].w;
    }
    sum += __shfl_xor_sync(0xffffffffu, sum, 1);
    sum += __shfl_xor_sync(0xffffffffu, sum, 2);
    float mean = sum * (1.0f / 128.0f);
    float q = 0.f;
#pragma unroll
    for (int k = 0; k < 8; k++) {
        float dx = v[k].x - mean, dy = v[k].y - mean, dz = v[k].z - mean, dw = v[k].w - mean;
        q += dx * dx + dy * dy + dz * dz + dw * dw;
    }
    q += __shfl_xor_sync(0xffffffffu, q, 1);
    q += __shfl_xor_sync(0xffffffffu, q, 2);
    float rstd = rsqrtf(q * (1.0f / 128.0f) + 1e-5f);

    size_t row = row0 + r;
    if (row < (size_t)M) {
#pragma unroll
        for (int k = 0; k < 8; k++) {
            int col = s * 4 + k * 16;
            float4 sc = *(const float4*)(lns + col), of = *(const float4*)(lno + col);
            float4 res = *(const float4*)(nf + row * 128 + col);
            float4 o;
            o.x = res.x + (v[k].x - mean) * rstd * sc.x + of.x;
            o.y = res.y + (v[k].y - mean) * rstd * sc.y + of.y;
            o.z = res.z + (v[k].z - mean) * rstd * sc.z + of.z;
            o.w = res.w + (v[k].w - mean) * rstd * sc.w + of.w;
            if (outf) *(float4*)(outf + row * 128 + col) = o;
            if (outh) {
                __half2 h0 = __floats2half2_rn(o.x, o.y), h1 = __floats2half2_rn(o.z, o.w);
                ((uint32_t*)(outh + row * 128 + col))[0] = *(uint32_t*)&h0;
                ((uint32_t*)(outh + row * 128 + col))[1] = *(uint32_t*)&h1;
            }
        }
    }
}

// =====================================================================================
extern "C" void kernel_launch(void* const* d_in, const int* in_sizes, int n_in,
                              void* d_out, int out_size)
{
    const float* nodes     = (const float*)d_in[0];
    const float* edges     = (const float*)d_in[1];
    const int*   senders   = (const int*)d_in[2];
    const int*   receivers = (const int*)d_in[3];
    const float* w_node    = (const float*)d_in[4];
    const float* b_node    = (const float*)d_in[5];
    const float* w_edge    = (const float*)d_in[6];
    const float* b_edge    = (const float*)d_in[7];
    const float* ln_n_s    = (const float*)d_in[8];
    const float* ln_n_o    = (const float*)d_in[9];
    const float* ln_e_s    = (const float*)d_in[10];
    const float* ln_e_o    = (const float*)d_in[11];
    const float* msg_w1    = (const float*)d_in[12];
    const float* msg_b1    = (const float*)d_in[13];
    const float* msg_w2    = (const float*)d_in[14];
    const float* msg_b2    = (const float*)d_in[15];
    const float* upd_w     = (const float*)d_in[16];
    const float* upd_b     = (const float*)d_in[17];
    const float* ln_s      = (const float*)d_in[18];
    const float* ln_o      = (const float*)d_in[19];

    const int N = in_sizes[0] / D;
    const int E = in_sizes[1] / D;

    float *pn, *pagg;
    __half *pnh, *peh, *pPs, *pPr, *pPe, *pwnt, *pwet, *pw1t, *pw2t, *pwut;
    cudaGetSymbolAddress((void**)&pn,   g_n);
    cudaGetSymbolAddress((void**)&pagg, g_agg);
    cudaGetSymbolAddress((void**)&pnh,  g_nh);
    cudaGetSymbolAddress((void**)&peh,  g_eh);
    cudaGetSymbolAddress((void**)&pPs,  g_Psh);
    cudaGetSymbolAddress((void**)&pPr,  g_Prh);
    cudaGetSymbolAddress((void**)&pPe,  g_Peh);
    cudaGetSymbolAddress((void**)&pwnt, g_wnt);
    cudaGetSymbolAddress((void**)&pwet, g_wet);
    cudaGetSymbolAddress((void**)&pw1t, g_w1t);
    cudaGetSymbolAddress((void**)&pw2t, g_w2t);
    cudaGetSymbolAddress((void**)&pwut, g_wut);

    const size_t embed_smem = 69632;
    const size_t gemm1_smem = 104448;
    const size_t edge_smem  = 136192;
    const size_t upd_smem   = 135168;

    cudaFuncSetAttribute(embed_f16,       cudaFuncAttributeMaxDynamicSharedMemorySize, (int)embed_smem);
    cudaFuncSetAttribute(gemm1_f16,       cudaFuncAttributeMaxDynamicSharedMemorySize, (int)gemm1_smem);
    cudaFuncSetAttribute(edge_msg_f16,    cudaFuncAttributeMaxDynamicSharedMemorySize, (int)edge_smem);
    cudaFuncSetAttribute(node_update_f16, cudaFuncAttributeMaxDynamicSharedMemorySize, (int)upd_smem);

    // ---- weight transposes (f32 [K][N] -> f16 [N][K]) ----
    dim3 tt(256);
    transpose_w<<<dim3(4, 4), tt>>>(w_node, pwnt, 128, 128);
    transpose_w<<<dim3(4, 4), tt>>>(w_edge, pwet, 128, 128);
    for (int l = 0; l < 3; l++) {
        for (int p = 0; p < 3; p++)
            transpose_w<<<dim3(4, 8), tt>>>(msg_w1 + (size_t)l * 384 * 256 + (size_t)p * 128 * 256,
                                            pw1t + (size_t)(l * 3 + p) * 256 * 128, 128, 256);
        transpose_w<<<dim3(8, 4), tt>>>(msg_w2 + (size_t)l * 256 * 128, pw2t + (size_t)l * 128 * 256, 256, 128);
        transpose_w<<<dim3(8, 4), tt>>>(upd_w + (size_t)l * 256 * 128, pwut + (size_t)l * 128 * 256, 256, 128);
    }

    // ---- embeddings ----
    embed_f16<<<(N + 127) / 128, 512, embed_smem>>>(nodes, pwnt, b_node, ln_n_s, ln_n_o, pn, pnh, N);
    embed_f16<<<(E + 127) / 128, 512, embed_smem>>>(edges, pwet, b_edge, ln_e_s, ln_e_o, (float*)nullptr, peh, E);

    // ---- layers ----
    for (int l = 0; l < 3; l++) {
        gemm1_f16<<<(N + 127) / 128, 512, gemm1_smem>>>(pnh, pw1t + (size_t)(l * 3 + 0) * 32768, pPs, N);
        gemm1_f16<<<(N + 127) / 128, 512, gemm1_smem>>>(pnh, pw1t + (size_t)(l * 3 + 1) * 32768, pPr, N);
        gemm1_f16<<<(E + 127) / 128, 512, gemm1_smem>>>(peh, pw1t + (size_t)(l * 3 + 2) * 32768, pPe, E);
        cudaMemsetAsync(pagg, 0, (size_t)N * D * sizeof(float), 0);
        edge_msg_f16<<<(E + 127) / 128, 512, edge_smem>>>(
            pPs, pPr, pPe, msg_b1 + (size_t)l * 256,
            pw2t + (size_t)l * 32768, msg_b2 + (size_t)l * 128,
            senders, receivers, pagg, E);
        float* nout = (l == 2) ? (float*)d_out : pn;
        __half* nhout = (l == 2) ? (__half*)nullptr : pnh;
        node_update_f16<<<(N + 127) / 128, 512, upd_smem>>>(
            pn, pnh, pagg, pwut + (size_t)l * 32768, upd_b + (size_t)l * 128,
            ln_s + (size_t)l * 128, ln_o + (size_t)l * 128, nout, nhout, N);
    }
}

// round 6
// speedup vs baseline: 5.6442x; 1.3731x over previous
#include <cuda_runtime.h>
#include <cuda_fp16.h>
#include <stdint.h>
#include <math.h>

#define N_NODES 50000
#define N_EDGES 800000
#define D 128
#define H 256

// ---------------- device scratch ----------------
__device__ __align__(16) float  g_n  [(size_t)N_NODES * D];
__device__ __align__(16) __half g_nh [(size_t)N_NODES * D];
__device__ __align__(16) __half g_eh [(size_t)N_EDGES * D];
__device__ __align__(16) __half g_Psh[(size_t)N_NODES * H];
__device__ __align__(16) __half g_Prh[(size_t)N_NODES * H];
__device__ __align__(16) float  g_agg[(size_t)N_NODES * D];
// pre-transposed fp16 weights ([N][K] K-major)
__device__ __align__(16) __half g_wnt[128 * 128];
__device__ __align__(16) __half g_wet[128 * 128];
__device__ __align__(16) __half g_w1t[9 * 256 * 128];
__device__ __align__(16) __half g_w2t[3 * 128 * 256];
__device__ __align__(16) __half g_wut[3 * 128 * 256];

__device__ __forceinline__ uint32_t s2u(const void* p) {
    uint32_t a;
    asm("{ .reg .u64 t; cvta.to.shared.u64 t, %1; cvt.u32.u64 %0, t; }" : "=r"(a) : "l"(p));
    return a;
}

__device__ __forceinline__ void ldsm4(uint32_t* r, uint32_t a) {
    asm volatile("ldmatrix.sync.aligned.m8n8.x4.shared.b16 {%0,%1,%2,%3}, [%4];"
        : "=r"(r[0]), "=r"(r[1]), "=r"(r[2]), "=r"(r[3]) : "r"(a));
}

__device__ __forceinline__ void mma16816(float* c, const uint32_t* a, uint32_t b0, uint32_t b1) {
    asm volatile("mma.sync.aligned.m16n8k16.row.col.f32.f16.f16.f32 "
        "{%0,%1,%2,%3},{%4,%5,%6,%7},{%8,%9},{%0,%1,%2,%3};"
        : "+f"(c[0]), "+f"(c[1]), "+f"(c[2]), "+f"(c[3])
        : "r"(a[0]), "r"(a[1]), "r"(a[2]), "r"(a[3]), "r"(b0), "r"(b1));
}

__device__ __forceinline__ float gelu_tanh(float x) {
    const float c = 0.7978845608028654f;
    float t = tanhf(c * (x + 0.044715f * x * x * x));
    return 0.5f * x * (1.0f + t);
}

// ------------- shared-memory GEMM core (padded rows: SA = K*2+16) -------------
template<int K, int NTW>
__device__ __forceinline__ void mma_loop(uint32_t abase, uint32_t bbase,
                                         float (&acc)[2][NTW][4], int wm, int wn, int lane)
{
    const int SA = K * 2 + 16;
    int mat  = lane >> 3;
    int arow = (lane & 7) + ((mat & 1) << 3);
    int akb  = (mat >> 1) << 4;
    int brow = (lane & 7) + ((mat >> 1) << 3);
    int bkb  = (mat & 1) << 4;
    uint32_t a0 = abase + (wm * 32 + arow) * SA + akb;
    uint32_t b0 = bbase + (wn * (8 * NTW) + brow) * SA + bkb;
#pragma unroll
    for (int kt = 0; kt < K / 16; kt++) {
        uint32_t A[2][4], B[NTW / 2][4];
        ldsm4(A[0], a0 + kt * 32);
        ldsm4(A[1], a0 + 16 * SA + kt * 32);
#pragma unroll
        for (int j = 0; j < NTW / 2; j++)
            ldsm4(B[j], b0 + j * 16 * SA + kt * 32);
#pragma unroll
        for (int i = 0; i < 2; i++)
#pragma unroll
            for (int j = 0; j < NTW / 2; j++) {
                mma16816(acc[i][2 * j],     A[i], B[j][0], B[j][1]);
                mma16816(acc[i][2 * j + 1], A[i], B[j][2], B[j][3]);
            }
    }
}

template<int K>
__device__ __forceinline__ void stage_rows(char* dst, const __half* src, size_t row0, int M)
{
    const int SA = K * 2 + 16, CH = K / 8;
    for (int i = threadIdx.x; i < 128 * CH; i += 512) {
        int r = i / CH, c = i % CH;
        uint4 v = make_uint4(0, 0, 0, 0);
        if (row0 + r < (size_t)M) v = *(const uint4*)(src + (row0 + r) * K + c * 8);
        *(uint4*)(dst + r * SA + c * 16) = v;
    }
}
template<int K>
__device__ __forceinline__ void stage_w(char* dst, const __half* src, int rows)
{
    const int SA = K * 2 + 16, CH = K / 8;
    for (int i = threadIdx.x; i < rows * CH; i += 512)
        *(uint4*)(dst + (i / CH) * SA + (i % CH) * 16) = ((const uint4*)src)[i];
}

// =====================================================================================
__global__ void transpose_w(const float* __restrict__ in, __half* __restrict__ out, int K, int N)
{
    __shared__ float t[32][33];
    int k0 = blockIdx.x * 32, n0 = blockIdx.y * 32;
    int tx = threadIdx.x & 31, ty = threadIdx.x >> 5;
    for (int i = ty; i < 32; i += 8) {
        int k = k0 + i, n = n0 + tx;
        t[i][tx] = (k < K && n < N) ? in[(size_t)k * N + n] : 0.f;
    }
    __syncthreads();
    for (int i = ty; i < 32; i += 8) {
        int n = n0 + i, k = k0 + tx;
        if (n < N && k < K) out[(size_t)n * K + k] = __float2half(t[tx][i]);
    }
}

// =====================================================================================
// embed: out = LN(gelu(x@W + b)). K=128, N=128.
// =====================================================================================
__global__ __launch_bounds__(512, 1)
void embed_f16(const float* __restrict__ x, const __half* __restrict__ Wt,
               const float* __restrict__ bias,
               const float* __restrict__ lns, const float* __restrict__ lno,
               float* __restrict__ outf, __half* __restrict__ outh, int M)
{
    extern __shared__ char sm[];
    char* Asm = sm;
    char* Bsm = sm + 34816;
    const int tid = threadIdx.x, w = tid >> 5, lane = tid & 31;
    const size_t row0 = (size_t)blockIdx.x * 128;

    for (int i = tid; i < 128 * 16; i += 512) {
        int r = i >> 4, c = i & 15;
        uint32_t o[4] = {0, 0, 0, 0};
        if (row0 + r < (size_t)M) {
            const float* src = x + (row0 + r) * 128 + c * 8;
            float4 a = ((const float4*)src)[0], b = ((const float4*)src)[1];
            __half2 h0 = __floats2half2_rn(a.x, a.y), h1 = __floats2half2_rn(a.z, a.w);
            __half2 h2 = __floats2half2_rn(b.x, b.y), h3 = __floats2half2_rn(b.z, b.w);
            o[0] = *(uint32_t*)&h0; o[1] = *(uint32_t*)&h1; o[2] = *(uint32_t*)&h2; o[3] = *(uint32_t*)&h3;
        }
        *(uint4*)(Asm + r * 272 + c * 16) = *(uint4*)o;
    }
    stage_w<128>(Bsm, Wt, 128);
    __syncthreads();

    float acc[2][4][4] = {};
    mma_loop<128, 4>(s2u(Asm), s2u(Bsm), acc, w >> 2, w & 3, lane);
    __syncthreads();

    float* Csm = (float*)sm;   // 128 x 132
    const int gid = lane >> 2, tig = lane & 3;
    const int rb = (w >> 2) * 32 + gid, cb = (w & 3) * 32 + tig * 2;
#pragma unroll
    for (int i = 0; i < 2; i++)
#pragma unroll
        for (int nt = 0; nt < 4; nt++) {
            int col = cb + nt * 8;
            int r = rb + i * 16;
            Csm[r * 132 + col]           = gelu_tanh(acc[i][nt][0] + bias[col]);
            Csm[r * 132 + col + 1]       = gelu_tanh(acc[i][nt][1] + bias[col + 1]);
            Csm[(r + 8) * 132 + col]     = gelu_tanh(acc[i][nt][2] + bias[col]);
            Csm[(r + 8) * 132 + col + 1] = gelu_tanh(acc[i][nt][3] + bias[col + 1]);
        }
    __syncthreads();

    int r = tid >> 2, s = tid & 3;
    float4 v[8];
    float sum = 0.f;
#pragma unroll
    for (int k = 0; k < 8; k++) {
        v[k] = *(float4*)&Csm[r * 132 + s * 4 + k * 16];
        sum += v[k].x + v[k].y + v[k].z + v[k].w;
    }
    sum += __shfl_xor_sync(0xffffffffu, sum, 1);
    sum += __shfl_xor_sync(0xffffffffu, sum, 2);
    float mean = sum * (1.0f / 128.0f);
    float q = 0.f;
#pragma unroll
    for (int k = 0; k < 8; k++) {
        float dx = v[k].x - mean, dy = v[k].y - mean, dz = v[k].z - mean, dw = v[k].w - mean;
        q += dx * dx + dy * dy + dz * dz + dw * dw;
    }
    q += __shfl_xor_sync(0xffffffffu, q, 1);
    q += __shfl_xor_sync(0xffffffffu, q, 2);
    float rstd = rsqrtf(q * (1.0f / 128.0f) + 1e-5f);

    size_t row = row0 + r;
    if (row < (size_t)M) {
#pragma unroll
        for (int k = 0; k < 8; k++) {
            int col = s * 4 + k * 16;
            float4 sc = *(const float4*)(lns + col), of = *(const float4*)(lno + col);
            float4 o;
            o.x = (v[k].x - mean) * rstd * sc.x + of.x;
            o.y = (v[k].y - mean) * rstd * sc.y + of.y;
            o.z = (v[k].z - mean) * rstd * sc.z + of.z;
            o.w = (v[k].w - mean) * rstd * sc.w + of.w;
            if (outf) *(float4*)(outf + row * 128 + col) = o;
            if (outh) {
                __half2 h0 = __floats2half2_rn(o.x, o.y), h1 = __floats2half2_rn(o.z, o.w);
                ((uint32_t*)(outh + row * 128 + col))[0] = *(uint32_t*)&h0;
                ((uint32_t*)(outh + row * 128 + col))[1] = *(uint32_t*)&h1;
            }
        }
    }
}

// =====================================================================================
// gemm1x2: C1 = A@B1t^T, C2 = A@B2t^T  (A [M,128] f16; B [256][128]; C f16 [M,256])
// A staged once. smem: A 34816 + B1 69632 + B2 69632 = 174080
// =====================================================================================
__global__ __launch_bounds__(512, 1)
void gemm1x2_f16(const __half* __restrict__ A,
                 const __half* __restrict__ B1t, const __half* __restrict__ B2t,
                 __half* __restrict__ C1, __half* __restrict__ C2, int M)
{
    extern __shared__ char sm[];
    char* Asm  = sm;
    char* Bsm1 = sm + 34816;
    char* Bsm2 = sm + 34816 + 69632;
    const int tid = threadIdx.x, w = tid >> 5, lane = tid & 31;
    const size_t row0 = (size_t)blockIdx.x * 128;

    stage_rows<128>(Asm, A, row0, M);
    stage_w<128>(Bsm1, B1t, 256);
    stage_w<128>(Bsm2, B2t, 256);
    __syncthreads();

    const int gid = lane >> 2, tig = lane & 3;
    const int rb = (w >> 2) * 32 + gid, cb = (w & 3) * 64 + tig * 2;

#pragma unroll
    for (int pass = 0; pass < 2; pass++) {
        float acc[2][8][4] = {};
        mma_loop<128, 8>(s2u(Asm), s2u(pass ? Bsm2 : Bsm1), acc, w >> 2, w & 3, lane);
        __half* C = pass ? C2 : C1;
#pragma unroll
        for (int i = 0; i < 2; i++) {
            size_t r = row0 + rb + i * 16;
#pragma unroll
            for (int nt = 0; nt < 8; nt++) {
                int col = cb + nt * 8;
                __half2 h01 = __floats2half2_rn(acc[i][nt][0], acc[i][nt][1]);
                __half2 h23 = __floats2half2_rn(acc[i][nt][2], acc[i][nt][3]);
                if (r < (size_t)M)     *(__half2*)(C + r * 256 + col) = h01;
                if (r + 8 < (size_t)M) *(__half2*)(C + (r + 8) * 256 + col) = h23;
            }
        }
    }
}

// =====================================================================================
// edge_fused (persistent): per 128-edge block:
//   Pe = eh@W1c^T (mma1, K=128,N=256)  -> smem f16
//   m1 = relu(Pe + Ps[s] + Pr[r] + b1) (in place)
//   out = m1@W2^T (mma2, K=256,N=128); agg[rcv] += relu(out + b2) (float4 atomics)
// smem: idx 1024 | B1 69632 | B2 67584 | WK 67584  = 205824
// =====================================================================================
__global__ __launch_bounds__(512, 1)
void edge_fused_f16(const __half* __restrict__ eh,
                    const __half* __restrict__ Ps, const __half* __restrict__ Pr,
                    const __half* __restrict__ W1ct, const float* __restrict__ b1,
                    const __half* __restrict__ W2t,  const float* __restrict__ b2,
                    const int* __restrict__ snd, const int* __restrict__ rcv,
                    float* __restrict__ agg, int E)
{
    extern __shared__ char sm[];
    int* sidx = (int*)sm;
    int* ridx = (int*)(sm + 512);
    char* B1 = sm + 1024;
    char* B2 = sm + 1024 + 69632;
    char* WK = sm + 1024 + 69632 + 67584;
    const int tid = threadIdx.x, w = tid >> 5, lane = tid & 31;
    const int gid = lane >> 2, tig = lane & 3;

    stage_w<128>(B1, W1ct, 256);
    stage_w<256>(B2, W2t, 128);
    __syncthreads();

    const int nblk = (E + 127) >> 7;
    for (int blk = blockIdx.x; blk < nblk; blk += gridDim.x) {
        const int e0 = blk << 7;
        if (tid < 128) {
            int eg = e0 + tid;
            sidx[tid] = (eg < E) ? snd[eg] : -1;
            ridx[tid] = (eg < E) ? rcv[eg] : -1;
        }
        stage_rows<128>(WK, eh, (size_t)e0, E);
        __syncthreads();

        // ---- mma1: Pe tile ----
        {
            float acc[2][8][4] = {};
            mma_loop<128, 8>(s2u(WK), s2u(B1), acc, w >> 2, w & 3, lane);
            __syncthreads();   // done reading WK as A_e
            const int rb = (w >> 2) * 32 + gid, cb = (w & 3) * 64 + tig * 2;
#pragma unroll
            for (int i = 0; i < 2; i++)
#pragma unroll
                for (int nt = 0; nt < 8; nt++) {
                    int col = cb + nt * 8;
                    int r = rb + i * 16;
                    __half2 h01 = __floats2half2_rn(acc[i][nt][0], acc[i][nt][1]);
                    __half2 h23 = __floats2half2_rn(acc[i][nt][2], acc[i][nt][3]);
                    *(__half2*)(WK + r * 528 + col * 2)       = h01;
                    *(__half2*)(WK + (r + 8) * 528 + col * 2) = h23;
                }
        }
        __syncthreads();

        // ---- gather + add + relu (in place) ----
        for (int i = tid; i < 128 * 32; i += 512) {
            int r = i >> 5, c = i & 31, k0 = c * 8;
            int sv = sidx[r], rv = ridx[r];
            if (sv >= 0) {
                uint4 pe = *(uint4*)(WK + r * 528 + c * 16);
                uint4 pa = *(const uint4*)(Ps + (size_t)sv * 256 + k0);
                uint4 pb = *(const uint4*)(Pr + (size_t)rv * 256 + k0);
                float bv[8];
                *(float4*)bv       = *(const float4*)(b1 + k0);
                *(float4*)(bv + 4) = *(const float4*)(b1 + k0 + 4);
                uint32_t o[4];
#pragma unroll
                for (int qq = 0; qq < 4; qq++) {
                    float2 fe = __half22float2(((const __half2*)&pe)[qq]);
                    float2 fa = __half22float2(((const __half2*)&pa)[qq]);
                    float2 fb = __half22float2(((const __half2*)&pb)[qq]);
                    float xx = fmaxf(fe.x + fa.x + fb.x + bv[2 * qq], 0.f);
                    float yy = fmaxf(fe.y + fa.y + fb.y + bv[2 * qq + 1], 0.f);
                    __half2 h = __floats2half2_rn(xx, yy);
                    o[qq] = *(uint32_t*)&h;
                }
                *(uint4*)(WK + r * 528 + c * 16) = *(uint4*)o;
            }
        }
        __syncthreads();

        // ---- mma2: out tile ----
        float acc2[2][4][4] = {};
        mma_loop<256, 4>(s2u(WK), s2u(B2), acc2, w >> 2, w & 3, lane);
        __syncthreads();   // done reading WK as m1

        float* Csm = (float*)WK;   // 128 x 132 f32
        {
            const int rb = (w >> 2) * 32 + gid, cb = (w & 3) * 32 + tig * 2;
#pragma unroll
            for (int i = 0; i < 2; i++)
#pragma unroll
                for (int nt = 0; nt < 4; nt++) {
                    int col = cb + nt * 8;
                    int r = rb + i * 16;
                    Csm[r * 132 + col]           = acc2[i][nt][0];
                    Csm[r * 132 + col + 1]       = acc2[i][nt][1];
                    Csm[(r + 8) * 132 + col]     = acc2[i][nt][2];
                    Csm[(r + 8) * 132 + col + 1] = acc2[i][nt][3];
                }
        }
        __syncthreads();

        // ---- scatter ----
        for (int i = tid; i < 128 * 32; i += 512) {
            int r = i >> 5, c4 = i & 31;
            int rv = ridx[r];
            if (rv >= 0) {
                float4 vv = *(float4*)&Csm[r * 132 + c4 * 4];
                float4 bb = ((const float4*)b2)[c4];
                float4 o;
                o.x = fmaxf(vv.x + bb.x, 0.f);
                o.y = fmaxf(vv.y + bb.y, 0.f);
                o.z = fmaxf(vv.z + bb.z, 0.f);
                o.w = fmaxf(vv.w + bb.w, 0.f);
                atomicAdd((float4*)(agg + (size_t)rv * 128 + c4 * 4), o);
            }
        }
        __syncthreads();   // WK/idx reused next iteration
    }
}

// =====================================================================================
// node_update: upd = LN(concat(nh, agg) @ Wu + b); out = n + upd. K=256, N=128.
// =====================================================================================
__global__ __launch_bounds__(512, 1)
void node_update_f16(const float* __restrict__ nf, const __half* __restrict__ nh,
                     const float* __restrict__ agg, const __half* __restrict__ Wut,
                     const float* __restrict__ bias,
                     const float* __restrict__ lns, const float* __restrict__ lno,
                     float* __restrict__ outf, __half* __restrict__ outh, int M)
{
    extern __shared__ char sm[];
    char* Asm = sm;
    char* Bsm = sm + 67584;
    const int tid = threadIdx.x, w = tid >> 5, lane = tid & 31;
    const size_t row0 = (size_t)blockIdx.x * 128;

    for (int i = tid; i < 128 * 32; i += 512) {
        int r = i >> 5, c = i & 31, k0 = c * 8;
        uint32_t o[4] = {0, 0, 0, 0};
        size_t row = row0 + r;
        if (row < (size_t)M) {
            if (k0 < 128) {
                *(uint4*)o = *(const uint4*)(nh + row * 128 + k0);
            } else {
                const float* src = agg + row * 128 + (k0 - 128);
                float4 a = ((const float4*)src)[0], b = ((const float4*)src)[1];
                __half2 h0 = __floats2half2_rn(a.x, a.y), h1 = __floats2half2_rn(a.z, a.w);
                __half2 h2 = __floats2half2_rn(b.x, b.y), h3 = __floats2half2_rn(b.z, b.w);
                o[0] = *(uint32_t*)&h0; o[1] = *(uint32_t*)&h1; o[2] = *(uint32_t*)&h2; o[3] = *(uint32_t*)&h3;
            }
        }
        *(uint4*)(Asm + r * 528 + c * 16) = *(uint4*)o;
    }
    stage_w<256>(Bsm, Wut, 128);
    __syncthreads();

    float acc[2][4][4] = {};
    mma_loop<256, 4>(s2u(Asm), s2u(Bsm), acc, w >> 2, w & 3, lane);
    __syncthreads();

    float* Csm = (float*)Asm;
    const int gid = lane >> 2, tig = lane & 3;
    const int rb = (w >> 2) * 32 + gid, cb = (w & 3) * 32 + tig * 2;
#pragma unroll
    for (int i = 0; i < 2; i++)
#pragma unroll
        for (int nt = 0; nt < 4; nt++) {
            int col = cb + nt * 8;
            int r = rb + i * 16;
            Csm[r * 132 + col]           = acc[i][nt][0] + bias[col];
            Csm[r * 132 + col + 1]       = acc[i][nt][1] + bias[col + 1];
            Csm[(r + 8) * 132 + col]     = acc[i][nt][2] + bias[col];
            Csm[(r + 8) * 132 + col + 1] = acc[i][nt][3] + bias[col + 1];
        }
    __syncthreads();

    int r = tid >> 2, s = tid & 3;
    float4 v[8];
    float sum = 0.f;
#pragma unroll
    for (int k = 0; k < 8; k++) {
        v[k] = *(float4*)&Csm[r * 132 + s * 4 + k * 16];
        sum += v[k].x + v[k].y + v[k].z + v[k].w;
    }
    sum += __shfl_xor_sync(0xffffffffu, sum, 1);
    sum += __shfl_xor_sync(0xffffffffu, sum, 2);
    float mean = sum * (1.0f / 128.0f);
    float q = 0.f;
#pragma unroll
    for (int k = 0; k < 8; k++) {
        float dx = v[k].x - mean, dy = v[k].y - mean, dz = v[k].z - mean, dw = v[k].w - mean;
        q += dx * dx + dy * dy + dz * dz + dw * dw;
    }
    q += __shfl_xor_sync(0xffffffffu, q, 1);
    q += __shfl_xor_sync(0xffffffffu, q, 2);
    float rstd = rsqrtf(q * (1.0f / 128.0f) + 1e-5f);

    size_t row = row0 + r;
    if (row < (size_t)M) {
#pragma unroll
        for (int k = 0; k < 8; k++) {
            int col = s * 4 + k * 16;
            float4 sc = *(const float4*)(lns + col), of = *(const float4*)(lno + col);
            float4 res = *(const float4*)(nf + row * 128 + col);
            float4 o;
            o.x = res.x + (v[k].x - mean) * rstd * sc.x + of.x;
            o.y = res.y + (v[k].y - mean) * rstd * sc.y + of.y;
            o.z = res.z + (v[k].z - mean) * rstd * sc.z + of.z;
            o.w = res.w + (v[k].w - mean) * rstd * sc.w + of.w;
            if (outf) *(float4*)(outf + row * 128 + col) = o;
            if (outh) {
                __half2 h0 = __floats2half2_rn(o.x, o.y), h1 = __floats2half2_rn(o.z, o.w);
                ((uint32_t*)(outh + row * 128 + col))[0] = *(uint32_t*)&h0;
                ((uint32_t*)(outh + row * 128 + col))[1] = *(uint32_t*)&h1;
            }
        }
    }
}

// =====================================================================================
extern "C" void kernel_launch(void* const* d_in, const int* in_sizes, int n_in,
                              void* d_out, int out_size)
{
    const float* nodes     = (const float*)d_in[0];
    const float* edges     = (const float*)d_in[1];
    const int*   senders   = (const int*)d_in[2];
    const int*   receivers = (const int*)d_in[3];
    const float* w_node    = (const float*)d_in[4];
    const float* b_node    = (const float*)d_in[5];
    const float* w_edge    = (const float*)d_in[6];
    const float* b_edge    = (const float*)d_in[7];
    const float* ln_n_s    = (const float*)d_in[8];
    const float* ln_n_o    = (const float*)d_in[9];
    const float* ln_e_s    = (const float*)d_in[10];
    const float* ln_e_o    = (const float*)d_in[11];
    const float* msg_w1    = (const float*)d_in[12];
    const float* msg_b1    = (const float*)d_in[13];
    const float* msg_w2    = (const float*)d_in[14];
    const float* msg_b2    = (const float*)d_in[15];
    const float* upd_w     = (const float*)d_in[16];
    const float* upd_b     = (const float*)d_in[17];
    const float* ln_s      = (const float*)d_in[18];
    const float* ln_o      = (const float*)d_in[19];

    const int N = in_sizes[0] / D;
    const int E = in_sizes[1] / D;

    int dev = 0, nsm = 148;
    cudaGetDevice(&dev);
    cudaDeviceGetAttribute(&nsm, cudaDevAttrMultiProcessorCount, dev);

    float *pn, *pagg;
    __half *pnh, *peh, *pPs, *pPr, *pwnt, *pwet, *pw1t, *pw2t, *pwut;
    cudaGetSymbolAddress((void**)&pn,   g_n);
    cudaGetSymbolAddress((void**)&pagg, g_agg);
    cudaGetSymbolAddress((void**)&pnh,  g_nh);
    cudaGetSymbolAddress((void**)&peh,  g_eh);
    cudaGetSymbolAddress((void**)&pPs,  g_Psh);
    cudaGetSymbolAddress((void**)&pPr,  g_Prh);
    cudaGetSymbolAddress((void**)&pwnt, g_wnt);
    cudaGetSymbolAddress((void**)&pwet, g_wet);
    cudaGetSymbolAddress((void**)&pw1t, g_w1t);
    cudaGetSymbolAddress((void**)&pw2t, g_w2t);
    cudaGetSymbolAddress((void**)&pwut, g_wut);

    const size_t embed_smem  = 69632;
    const size_t g12_smem    = 174080;
    const size_t fused_smem  = 205824;
    const size_t upd_smem    = 135168;

    cudaFuncSetAttribute(embed_f16,       cudaFuncAttributeMaxDynamicSharedMemorySize, (int)embed_smem);
    cudaFuncSetAttribute(gemm1x2_f16,     cudaFuncAttributeMaxDynamicSharedMemorySize, (int)g12_smem);
    cudaFuncSetAttribute(edge_fused_f16,  cudaFuncAttributeMaxDynamicSharedMemorySize, (int)fused_smem);
    cudaFuncSetAttribute(node_update_f16, cudaFuncAttributeMaxDynamicSharedMemorySize, (int)upd_smem);

    // ---- weight transposes (f32 [K][N] -> f16 [N][K]) ----
    dim3 tt(256);
    transpose_w<<<dim3(4, 4), tt>>>(w_node, pwnt, 128, 128);
    transpose_w<<<dim3(4, 4), tt>>>(w_edge, pwet, 128, 128);
    for (int l = 0; l < 3; l++) {
        for (int p = 0; p < 3; p++)
            transpose_w<<<dim3(4, 8), tt>>>(msg_w1 + (size_t)l * 384 * 256 + (size_t)p * 128 * 256,
                                            pw1t + (size_t)(l * 3 + p) * 256 * 128, 128, 256);
        transpose_w<<<dim3(8, 4), tt>>>(msg_w2 + (size_t)l * 256 * 128, pw2t + (size_t)l * 128 * 256, 256, 128);
        transpose_w<<<dim3(8, 4), tt>>>(upd_w + (size_t)l * 256 * 128, pwut + (size_t)l * 128 * 256, 256, 128);
    }

    // ---- embeddings ----
    embed_f16<<<(N + 127) / 128, 512, embed_smem>>>(nodes, pwnt, b_node, ln_n_s, ln_n_o, pn, pnh, N);
    embed_f16<<<(E + 127) / 128, 512, embed_smem>>>(edges, pwet, b_edge, ln_e_s, ln_e_o, (float*)nullptr, peh, E);

    // ---- layers ----
    for (int l = 0; l < 3; l++) {
        gemm1x2_f16<<<(N + 127) / 128, 512, g12_smem>>>(
            pnh, pw1t + (size_t)(l * 3 + 0) * 32768, pw1t + (size_t)(l * 3 + 1) * 32768,
            pPs, pPr, N);
        cudaMemsetAsync(pagg, 0, (size_t)N * D * sizeof(float), 0);
        edge_fused_f16<<<nsm, 512, fused_smem>>>(
            peh, pPs, pPr,
            pw1t + (size_t)(l * 3 + 2) * 32768, msg_b1 + (size_t)l * 256,
            pw2t + (size_t)l * 32768, msg_b2 + (size_t)l * 128,
            senders, receivers, pagg, E);
        float* nout = (l == 2) ? (float*)d_out : pn;
        __half* nhout = (l == 2) ? (__half*)nullptr : pnh;
        node_update_f16<<<(N + 127) / 128, 512, upd_smem>>>(
            pn, pnh, pagg, pwut + (size_t)l * 32768, upd_b + (size_t)l * 128,
            ln_s + (size_t)l * 128, ln_o + (size_t)l * 128, nout, nhout, N);
    }
}